// round 12
// baseline (speedup 1.0000x reference)
#include <cuda_runtime.h>
#include <cstdint>
#include <math.h>

#define Bsz 2
#define Lsz 1024
#define Vsz 50257
#define NT  256
#define NROWS (Bsz * Lsz)
#define NSTAGE 8
#define STAGE_F4 256            // float4 per stage (== NT)
#define NFULL 49                // (Vsz-head)>>2>>8 == 49 for all head in 0..3
#define BETA 0.04f
#define EPS_LOW 0.2f
#define EPS_HIGH 0.2f

__device__ float g_logp[NROWS];
__device__ unsigned int g_count = 0;

__device__ __forceinline__ float warp_sum(float v) {
    #pragma unroll
    for (int o = 16; o > 0; o >>= 1) v += __shfl_xor_sync(0xFFFFFFFFu, v, o);
    return v;
}

__device__ __forceinline__ void cp_async16(unsigned int smem_addr, const void* gptr) {
    asm volatile("cp.async.cg.shared.global [%0], [%1], 16;\n"
                 :: "r"(smem_addr), "l"(gptr));
}
__device__ __forceinline__ void cp_commit() {
    asm volatile("cp.async.commit_group;\n");
}
__device__ __forceinline__ void cp_wait7() {
    asm volatile("cp.async.wait_group 7;\n");
}

__global__ __launch_bounds__(NT, 6)   // force <=42 regs -> 6 CTAs/SM (was 5, regfile-limited)
void grpo_kernel(const float* __restrict__ logits,
                 const int* __restrict__ cids,
                 const float* __restrict__ adv,
                 const float* __restrict__ old_lp,
                 const float* __restrict__ ref_lp,
                 const int* __restrict__ cmask,
                 float* __restrict__ out) {
    __shared__ float4 buf[NSTAGE * STAGE_F4];     // 32 KB ring

    const int row = blockIdx.x;
    const int b = row >> 10;
    const int l = row & (Lsz - 1);
    const size_t off = ((size_t)(b * (Lsz + 1) + l)) * (size_t)Vsz;
    const float* __restrict__ p = logits + off;
    const int tid = threadIdx.x;

    float s0 = 0.f, s1 = 0.f, s2 = 0.f, s3 = 0.f;

    // head so that p+head is 16B aligned
    const int head = (int)((4 - (off & 3)) & 3);
    if (tid < head) s0 += __expf(p[tid]);

    const int nv = (Vsz - head) >> 2;              // 12563 or 12564; nv>>8 == 49 always
    const float4* __restrict__ p4 = (const float4*)(p + head);

    unsigned int smem_base;
    {
        unsigned int a;
        asm("{ .reg .u64 t; cvta.to.shared.u64 t, %1; cvt.u32.u64 %0, t; }"
            : "=r"(a) : "l"((const void*)buf));
        smem_base = a;
    }
    const unsigned int smem_my = smem_base + (unsigned int)tid * 16u;
    const float4* gsrc = p4 + tid;                 // advances by STAGE_F4 per stage

    // prologue: fill 8 stages
    #pragma unroll
    for (int s = 0; s < NSTAGE; s++) {
        cp_async16(smem_my + (unsigned int)(s * (STAGE_F4 * 16)),
                   (const void*)(gsrc + s * STAGE_F4));
        cp_commit();
    }

    // main: s = 0..40, prefetch s+8 (always valid). slot addresses become
    // immediates under unrolling; producer==consumer so no barriers.
    #pragma unroll 8
    for (int s = 0; s < NFULL - NSTAGE; s++) {
        cp_wait7();
        const int slot = s & (NSTAGE - 1);
        float4 v = buf[slot * STAGE_F4 + tid];
        s0 += __expf(v.x); s1 += __expf(v.y); s2 += __expf(v.z); s3 += __expf(v.w);
        cp_async16(smem_my + (unsigned int)(slot * (STAGE_F4 * 16)),
                   (const void*)(gsrc + (s + NSTAGE) * STAGE_F4));
        cp_commit();
    }

    // drain: s = 41..48, no prefetch; empty commits keep group counting aligned
    #pragma unroll
    for (int s = NFULL - NSTAGE; s < NFULL; s++) {
        cp_wait7();
        const int slot = s & (NSTAGE - 1);
        float4 v = buf[slot * STAGE_F4 + tid];
        s0 += __expf(v.x); s1 += __expf(v.y); s2 += __expf(v.z); s3 += __expf(v.w);
        cp_commit();
    }

    // remainder float4s beyond 49*256
    for (int i = NFULL * STAGE_F4 + tid; i < nv; i += NT) {
        float4 v = __ldcs(p4 + i);
        s0 += __expf(v.x); s1 += __expf(v.y); s2 += __expf(v.z); s3 += __expf(v.w);
    }
    // scalar tail
    const int done = head + (nv << 2);
    for (int k = done + tid; k < Vsz; k += NT) s0 += __expf(p[k]);

    float S = (s0 + s1) + (s2 + s3);

    __shared__ float red[NT / 32];
    S = warp_sum(S);
    if ((tid & 31) == 0) red[tid >> 5] = S;
    __syncthreads();
    if (tid == 0) {
        float tot = 0.f;
        #pragma unroll
        for (int w = 0; w < NT / 32; w++) tot += red[w];
        float lse = logf(tot);
        float tok = p[cids[row]];
        g_logp[row] = tok - lse;
    }

    // last-block finalize (deterministic fixed-order reduction)
    __shared__ int isLast;
    if (tid == 0) {
        __threadfence();
        unsigned int v = atomicAdd(&g_count, 1u);
        isLast = (v == NROWS - 1);
        if (isLast) g_count = 0;
    }
    __syncthreads();
    if (!isLast) return;

    float kl_sum = 0.f, clip_sum = 0.f, mask_tot = 0.f;
    float loss_b0 = 0.f, loss_b1 = 0.f, mask_b0 = 0.f, mask_b1 = 0.f;

    #pragma unroll
    for (int k = 0; k < NROWS / NT; k++) {
        int idx = k * NT + tid;
        int bb = idx >> 10;
        float lp = g_logp[idx];
        float mk = (float)cmask[idx];
        float a  = adv[bb];
        float c1 = expf(lp - old_lp[idx]);
        float c2 = fminf(fmaxf(c1, 1.0f - EPS_LOW), 1.0f + EPS_HIGH);
        float ptl = -fminf(c1 * a, c2 * a);
        float d  = ref_lp[idx] - lp;
        float kl = expf(d) - d - 1.0f;
        ptl += BETA * kl;
        bool clipped = ((c1 < 1.0f - EPS_LOW) && (a < 0.f)) ||
                       ((c1 > 1.0f + EPS_HIGH) && (a > 0.f));
        kl_sum   += kl * mk;
        clip_sum += (clipped ? 1.0f : 0.0f) * mk;
        mask_tot += mk;
        if (bb == 0) { loss_b0 += ptl * mk; mask_b0 += mk; }
        else         { loss_b1 += ptl * mk; mask_b1 += mk; }
    }

    __shared__ float acc[7][NT / 32];
    float vals[7] = {kl_sum, clip_sum, mask_tot, loss_b0, loss_b1, mask_b0, mask_b1};
    #pragma unroll
    for (int j = 0; j < 7; j++) {
        float r = warp_sum(vals[j]);
        if ((tid & 31) == 0) acc[j][tid >> 5] = r;
    }
    __syncthreads();
    if (tid == 0) {
        float tot[7];
        #pragma unroll
        for (int j = 0; j < 7; j++) {
            float t = 0.f;
            #pragma unroll
            for (int w = 0; w < NT / 32; w++) t += acc[j][w];
            tot[j] = t;
        }
        float ms = fmaxf(tot[2], 1.0f);
        out[0] = 0.5f * (tot[3] / fmaxf(tot[5], 1.0f) + tot[4] / fmaxf(tot[6], 1.0f));
        out[1] = tot[0] / ms;
        out[2] = tot[1] / ms;
    }
}

extern "C" void kernel_launch(void* const* d_in, const int* in_sizes, int n_in,
                              void* d_out, int out_size) {
    const float* logits = (const float*)d_in[0];
    const int*   cids   = (const int*)d_in[1];
    const float* adv    = (const float*)d_in[2];
    const float* old_lp = (const float*)d_in[3];
    const float* ref_lp = (const float*)d_in[4];
    const int*   cmask  = (const int*)d_in[5];
    float* out = (float*)d_out;

    grpo_kernel<<<NROWS, NT>>>(logits, cids, adv, old_lp, ref_lp, cmask, out);
}

// round 14
// speedup vs baseline: 1.0064x; 1.0064x over previous
#include <cuda_runtime.h>
#include <cstdint>
#include <math.h>

#define Bsz 2
#define Lsz 1024
#define Vsz 50257
#define NT  256
#define NROWS (Bsz * Lsz)
#define NSTAGE 8
#define STAGE_F4 256            // float4 per stage (== NT)
#define NFULL 49                // (Vsz-head)>>2>>8 == 49 for all head in 0..3
#define S_MID 25                // half0: stages [0,25), half1: [25,49) + tails
#define BETA 0.04f
#define EPS_LOW 0.2f
#define EPS_HIGH 0.2f

__device__ float g_logp[NROWS];
__device__ float g_partial[NROWS * 2];
__device__ unsigned int g_rowcnt[NROWS];   // zero-init; reset to 0 after each combine
__device__ unsigned int g_count = 0;

__device__ __forceinline__ float warp_sum(float v) {
    #pragma unroll
    for (int o = 16; o > 0; o >>= 1) v += __shfl_xor_sync(0xFFFFFFFFu, v, o);
    return v;
}

__device__ __forceinline__ void cp_async16(unsigned int smem_addr, const void* gptr) {
    asm volatile("cp.async.cg.shared.global [%0], [%1], 16;\n"
                 :: "r"(smem_addr), "l"(gptr));
}
__device__ __forceinline__ void cp_commit() {
    asm volatile("cp.async.commit_group;\n");
}
__device__ __forceinline__ void cp_wait7() {
    asm volatile("cp.async.wait_group 7;\n");
}

__global__ __launch_bounds__(NT)
void grpo_kernel(const float* __restrict__ logits,
                 const int* __restrict__ cids,
                 const float* __restrict__ adv,
                 const float* __restrict__ old_lp,
                 const float* __restrict__ ref_lp,
                 const int* __restrict__ cmask,
                 float* __restrict__ out) {
    __shared__ float4 buf[NSTAGE * STAGE_F4];     // 32 KB ring

    const int row  = blockIdx.x >> 1;
    const int half = blockIdx.x & 1;
    const int b = row >> 10;
    const int l = row & (Lsz - 1);
    const size_t off = ((size_t)(b * (Lsz + 1) + l)) * (size_t)Vsz;
    const float* __restrict__ p = logits + off;
    const int tid = threadIdx.x;

    float s0 = 0.f, s1 = 0.f, s2 = 0.f, s3 = 0.f;

    const int head = (int)((4 - (off & 3)) & 3);
    const int nv = (Vsz - head) >> 2;              // 12563/12564; >>8 == 49 always
    const float4* __restrict__ p4 = (const float4*)(p + head);

    unsigned int smem_base;
    {
        unsigned int a;
        asm("{ .reg .u64 t; cvta.to.shared.u64 t, %1; cvt.u32.u64 %0, t; }"
            : "=r"(a) : "l"((const void*)buf));
        smem_base = a;
    }
    const unsigned int smem_my = smem_base + (unsigned int)tid * 16u;
    const float4* gsrc = p4 + tid;

    if (half == 0) {
        // head elements
        if (tid < head) s0 += __expf(p[tid]);
        // stages [0, 25)
        #pragma unroll
        for (int s = 0; s < NSTAGE; s++) {
            cp_async16(smem_my + (unsigned int)(s * (STAGE_F4 * 16)),
                       (const void*)(gsrc + s * STAGE_F4));
            cp_commit();
        }
        #pragma unroll 8
        for (int s = 0; s < S_MID - NSTAGE; s++) {
            cp_wait7();
            const int slot = s & (NSTAGE - 1);
            float4 v = buf[slot * STAGE_F4 + tid];
            s0 += __expf(v.x); s1 += __expf(v.y); s2 += __expf(v.z); s3 += __expf(v.w);
            cp_async16(smem_my + (unsigned int)(slot * (STAGE_F4 * 16)),
                       (const void*)(gsrc + (s + NSTAGE) * STAGE_F4));
            cp_commit();
        }
        #pragma unroll
        for (int s = S_MID - NSTAGE; s < S_MID; s++) {
            cp_wait7();
            const int slot = s & (NSTAGE - 1);
            float4 v = buf[slot * STAGE_F4 + tid];
            s0 += __expf(v.x); s1 += __expf(v.y); s2 += __expf(v.z); s3 += __expf(v.w);
            cp_commit();
        }
    } else {
        // stages [25, 49)
        #pragma unroll
        for (int s = S_MID; s < S_MID + NSTAGE; s++) {
            cp_async16(smem_my + (unsigned int)(((s - S_MID) & (NSTAGE - 1)) * (STAGE_F4 * 16)),
                       (const void*)(gsrc + s * STAGE_F4));
            cp_commit();
        }
        #pragma unroll 8
        for (int s = S_MID; s < NFULL - NSTAGE; s++) {
            cp_wait7();
            const int slot = (s - S_MID) & (NSTAGE - 1);
            float4 v = buf[slot * STAGE_F4 + tid];
            s0 += __expf(v.x); s1 += __expf(v.y); s2 += __expf(v.z); s3 += __expf(v.w);
            cp_async16(smem_my + (unsigned int)(slot * (STAGE_F4 * 16)),
                       (const void*)(gsrc + (s + NSTAGE) * STAGE_F4));
            cp_commit();
        }
        #pragma unroll
        for (int s = NFULL - NSTAGE; s < NFULL; s++) {
            cp_wait7();
            const int slot = (s - S_MID) & (NSTAGE - 1);
            float4 v = buf[slot * STAGE_F4 + tid];
            s0 += __expf(v.x); s1 += __expf(v.y); s2 += __expf(v.z); s3 += __expf(v.w);
            cp_commit();
        }
        // remainder float4s beyond 49*256
        for (int i = NFULL * STAGE_F4 + tid; i < nv; i += NT) {
            float4 v = __ldcs(p4 + i);
            s0 += __expf(v.x); s1 += __expf(v.y); s2 += __expf(v.z); s3 += __expf(v.w);
        }
        // scalar tail
        const int done = head + (nv << 2);
        for (int k = done + tid; k < Vsz; k += NT) s0 += __expf(p[k]);
    }

    float S = (s0 + s1) + (s2 + s3);

    __shared__ float red[NT / 32];
    S = warp_sum(S);
    if ((tid & 31) == 0) red[tid >> 5] = S;
    __syncthreads();

    __shared__ int isLast;
    if (tid == 0) {
        float tot = 0.f;
        #pragma unroll
        for (int w = 0; w < NT / 32; w++) tot += red[w];

        // publish partial, combine if second
        *(volatile float*)&g_partial[2 * row + half] = tot;
        __threadfence();
        unsigned int rc = atomicAdd(&g_rowcnt[row], 1u);
        int last = 0;
        if (rc == 1) {
            __threadfence();
            float P0 = *(volatile float*)&g_partial[2 * row];
            float P1 = *(volatile float*)&g_partial[2 * row + 1];
            float lse = logf(P0 + P1);      // fixed order: deterministic
            g_logp[row] = p[cids[row]] - lse;
            g_rowcnt[row] = 0;              // reset for next graph replay
            __threadfence();
            unsigned int v = atomicAdd(&g_count, 1u);
            last = (v == NROWS - 1);
            if (last) g_count = 0;
        }
        isLast = last;
    }
    __syncthreads();
    if (!isLast) return;

    float kl_sum = 0.f, clip_sum = 0.f, mask_tot = 0.f;
    float loss_b0 = 0.f, loss_b1 = 0.f, mask_b0 = 0.f, mask_b1 = 0.f;

    #pragma unroll
    for (int k = 0; k < NROWS / NT; k++) {
        int idx = k * NT + tid;
        int bb = idx >> 10;
        float lp = g_logp[idx];
        float mk = (float)cmask[idx];
        float a  = adv[bb];
        float c1 = expf(lp - old_lp[idx]);
        float c2 = fminf(fmaxf(c1, 1.0f - EPS_LOW), 1.0f + EPS_HIGH);
        float ptl = -fminf(c1 * a, c2 * a);
        float d  = ref_lp[idx] - lp;
        float kl = expf(d) - d - 1.0f;
        ptl += BETA * kl;
        bool clipped = ((c1 < 1.0f - EPS_LOW) && (a < 0.f)) ||
                       ((c1 > 1.0f + EPS_HIGH) && (a > 0.f));
        kl_sum   += kl * mk;
        clip_sum += (clipped ? 1.0f : 0.0f) * mk;
        mask_tot += mk;
        if (bb == 0) { loss_b0 += ptl * mk; mask_b0 += mk; }
        else         { loss_b1 += ptl * mk; mask_b1 += mk; }
    }

    __shared__ float acc[7][NT / 32];
    float vals[7] = {kl_sum, clip_sum, mask_tot, loss_b0, loss_b1, mask_b0, mask_b1};
    #pragma unroll
    for (int j = 0; j < 7; j++) {
        float r = warp_sum(vals[j]);
        if ((tid & 31) == 0) acc[j][tid >> 5] = r;
    }
    __syncthreads();
    if (tid == 0) {
        float tot[7];
        #pragma unroll
        for (int j = 0; j < 7; j++) {
            float t = 0.f;
            #pragma unroll
            for (int w = 0; w < NT / 32; w++) t += acc[j][w];
            tot[j] = t;
        }
        float ms = fmaxf(tot[2], 1.0f);
        out[0] = 0.5f * (tot[3] / fmaxf(tot[5], 1.0f) + tot[4] / fmaxf(tot[6], 1.0f));
        out[1] = tot[0] / ms;
        out[2] = tot[1] / ms;
    }
}

extern "C" void kernel_launch(void* const* d_in, const int* in_sizes, int n_in,
                              void* d_out, int out_size) {
    const float* logits = (const float*)d_in[0];
    const int*   cids   = (const int*)d_in[1];
    const float* adv    = (const float*)d_in[2];
    const float* old_lp = (const float*)d_in[3];
    const float* ref_lp = (const float*)d_in[4];
    const int*   cmask  = (const int*)d_in[5];
    float* out = (float*)d_out;

    grpo_kernel<<<NROWS * 2, NT>>>(logits, cids, adv, old_lp, ref_lp, cmask, out);
}